// round 2
// baseline (speedup 1.0000x reference)
#include <cuda_runtime.h>

#define DD 13      // input feature dim
#define HH 32      // hidden dim
#define FF 45      // H + D
#define FP 48      // padded feat row
#define K1 64      // 2H (edge MLP hidden)
#define GG 128     // graphs
#define NMAX 50000

// ---------------- device scratch (no allocations allowed) ----------------
__device__ float g_sum[DD];
__device__ float g_sumsq[DD];
__device__ float g_mean[DD];
__device__ float g_istd[DD];
__device__ float g_feat[NMAX * FP];     // [Hn(32), X(13), pad(3)] per node
__device__ float g_acc[NMAX * HH];      // edge-message segment sums
__device__ float g_wc1T[K1 * FP];       // combined weight (xi part), k-major, padded
__device__ float g_wc2T[K1 * FP];       // combined weight (xj part), k-major, padded
__device__ float g_gsum[GG * FP];
__device__ int   g_gcnt[GG];

__device__ __forceinline__ float tanh_fast(float x) {
    float y;
    asm("tanh.approx.f32 %0, %1;" : "=f"(y) : "f"(x));
    return y;
}

// ---------------- 1) zero scratch ----------------
__global__ void zero_kernel(int accN) {
    int i = blockIdx.x * blockDim.x + threadIdx.x;
    int stride = gridDim.x * blockDim.x;
    for (int j = i; j < accN; j += stride) g_acc[j] = 0.f;
    if (i < DD) { g_sum[i] = 0.f; g_sumsq[i] = 0.f; }
    if (i < GG * FP) g_gsum[i] = 0.f;
    if (i < GG) g_gcnt[i] = 0;
}

// ---------------- 2) batchnorm statistics ----------------
__global__ void bn_stats(const float* __restrict__ x, int n) {
    float s[DD], s2[DD];
#pragma unroll
    for (int d = 0; d < DD; d++) { s[d] = 0.f; s2[d] = 0.f; }
    for (int i = blockIdx.x * blockDim.x + threadIdx.x; i < n;
         i += gridDim.x * blockDim.x) {
#pragma unroll
        for (int d = 0; d < DD; d++) {
            float v = x[i * DD + d];
            s[d] += v; s2[d] += v * v;
        }
    }
#pragma unroll
    for (int d = 0; d < DD; d++) {
        for (int off = 16; off > 0; off >>= 1) {
            s[d]  += __shfl_down_sync(0xffffffffu, s[d], off);
            s2[d] += __shfl_down_sync(0xffffffffu, s2[d], off);
        }
    }
    if ((threadIdx.x & 31) == 0) {
#pragma unroll
        for (int d = 0; d < DD; d++) {
            atomicAdd(&g_sum[d], s[d]);
            atomicAdd(&g_sumsq[d], s2[d]);
        }
    }
}

// ---------------- 3) finalize stats + build combined/transposed conv_w1 ----------------
// h1[k] = sum_a xi[a]*(W[a][k]-W[45+a][k]) + sum_a xj[a]*W[45+a][k]
__global__ void prep_kernel(const float* __restrict__ conv_w1, float invN) {
    int tid = threadIdx.x;
    if (tid < DD) {
        float mu  = g_sum[tid] * invN;
        float var = g_sumsq[tid] * invN - mu * mu;
        g_mean[tid] = mu;
        g_istd[tid] = rsqrtf(var + 1e-5f);
    }
    for (int i = tid; i < K1 * FP; i += blockDim.x) {
        int k = i / FP, a = i % FP;
        float wa = 0.f, wb = 0.f;
        if (a < FF) {
            float w0 = conv_w1[a * K1 + k];
            float w1 = conv_w1[(FF + a) * K1 + k];
            wa = w0 - w1;
            wb = w1;
        }
        g_wc1T[i] = wa;
        g_wc2T[i] = wb;
    }
}

// ---------------- 4) node MLP: BN-normalize + inputnet, write feat ----------------
__global__ void node_kernel(const float* __restrict__ x,
                            const float* __restrict__ gamma,
                            const float* __restrict__ beta,
                            const float* __restrict__ w1,
                            const float* __restrict__ b1,
                            const float* __restrict__ w2,
                            const float* __restrict__ b2,
                            int n) {
    __shared__ float s_w1[DD * HH], s_w2[HH * HH], s_b1[HH], s_b2[HH];
    __shared__ float s_gam[DD], s_bet[DD], s_mu[DD], s_is[DD];
    for (int i = threadIdx.x; i < DD * HH; i += blockDim.x) s_w1[i] = w1[i];
    for (int i = threadIdx.x; i < HH * HH; i += blockDim.x) s_w2[i] = w2[i];
    if (threadIdx.x < HH) { s_b1[threadIdx.x] = b1[threadIdx.x]; s_b2[threadIdx.x] = b2[threadIdx.x]; }
    if (threadIdx.x < DD) {
        s_gam[threadIdx.x] = gamma[threadIdx.x];
        s_bet[threadIdx.x] = beta[threadIdx.x];
        s_mu[threadIdx.x]  = g_mean[threadIdx.x];
        s_is[threadIdx.x]  = g_istd[threadIdx.x];
    }
    __syncthreads();
    int nn = blockIdx.x * blockDim.x + threadIdx.x;
    if (nn >= n) return;

    float X[DD];
#pragma unroll
    for (int d = 0; d < DD; d++)
        X[d] = (x[nn * DD + d] - s_mu[d]) * s_is[d] * s_gam[d] + s_bet[d];

    float h[HH];
#pragma unroll
    for (int j = 0; j < HH; j++) {
        float t = s_b1[j];
#pragma unroll
        for (int d = 0; d < DD; d++) t = fmaf(X[d], s_w1[d * HH + j], t);
        h[j] = fmaxf(t, 0.f);
    }
    float* outp = g_feat + (size_t)nn * FP;
#pragma unroll
    for (int j = 0; j < HH; j++) {
        float t = s_b2[j];
#pragma unroll
        for (int k = 0; k < HH; k++) t = fmaf(h[k], s_w2[k * HH + j], t);
        outp[j] = tanh_fast(t);
    }
#pragma unroll
    for (int d = 0; d < DD; d++) outp[HH + d] = X[d];
    outp[45] = 0.f; outp[46] = 0.f; outp[47] = 0.f;
}

// ---------------- 5) edge MLP + scatter-add (the hot kernel) ----------------
__global__ void __launch_bounds__(128, 3)
edge_kernel(const int* __restrict__ ei,
            const float* __restrict__ conv_b1,
            const float* __restrict__ conv_w2,
            const float* __restrict__ conv_b2,
            int E) {
    __shared__ float s_wc1[K1 * FP], s_wc2[K1 * FP], s_w2[K1 * HH];
    __shared__ float s_b1[K1], s_b2[HH];
    for (int i = threadIdx.x; i < K1 * FP; i += blockDim.x) {
        s_wc1[i] = g_wc1T[i];
        s_wc2[i] = g_wc2T[i];
    }
    for (int i = threadIdx.x; i < K1 * HH; i += blockDim.x) s_w2[i] = conv_w2[i];
    if (threadIdx.x < K1) s_b1[threadIdx.x] = conv_b1[threadIdx.x];
    if (threadIdx.x < HH) s_b2[threadIdx.x] = conv_b2[threadIdx.x];
    __syncthreads();

    for (int e = blockIdx.x * blockDim.x + threadIdx.x; e < E;
         e += gridDim.x * blockDim.x) {
        int src = ei[e];
        int dst = ei[E + e];
        float4 xi[12], xj[12];
        const float4* fi = (const float4*)(g_feat + (size_t)dst * FP);
        const float4* fj = (const float4*)(g_feat + (size_t)src * FP);
#pragma unroll
        for (int q = 0; q < 12; q++) { xi[q] = fi[q]; xj[q] = fj[q]; }

        float h2[HH];
#pragma unroll
        for (int j = 0; j < HH; j++) h2[j] = s_b2[j];

#pragma unroll 4
        for (int k = 0; k < K1; k++) {
            const float4* wa = (const float4*)(s_wc1 + k * FP);
            const float4* wb = (const float4*)(s_wc2 + k * FP);
            float a0 = 0.f, a1 = 0.f, a2 = 0.f, a3 = 0.f;
#pragma unroll
            for (int q = 0; q < 12; q++) {
                float4 w = wa[q], v = xi[q];
                a0 = fmaf(v.x, w.x, a0);
                a1 = fmaf(v.y, w.y, a1);
                a2 = fmaf(v.z, w.z, a2);
                a3 = fmaf(v.w, w.w, a3);
                w = wb[q]; v = xj[q];
                a0 = fmaf(v.x, w.x, a0);
                a1 = fmaf(v.y, w.y, a1);
                a2 = fmaf(v.z, w.z, a2);
                a3 = fmaf(v.w, w.w, a3);
            }
            float t = fmaxf((a0 + a1) + (a2 + a3) + s_b1[k], 0.f);
            const float4* w2r = (const float4*)(s_w2 + k * HH);
#pragma unroll
            for (int q = 0; q < 8; q++) {
                float4 w = w2r[q];
                h2[4 * q + 0] = fmaf(t, w.x, h2[4 * q + 0]);
                h2[4 * q + 1] = fmaf(t, w.y, h2[4 * q + 1]);
                h2[4 * q + 2] = fmaf(t, w.z, h2[4 * q + 2]);
                h2[4 * q + 3] = fmaf(t, w.w, h2[4 * q + 3]);
            }
        }
        float* ap = g_acc + (size_t)dst * HH;
#pragma unroll
        for (int j = 0; j < HH; j++) atomicAdd(ap + j, tanh_fast(h2[j]));
    }
}

// ---------------- 6) global mean pool (sums + counts) ----------------
__global__ void pool_kernel(const int* __restrict__ batch, int n) {
    int nn = blockIdx.x * blockDim.x + threadIdx.x;
    if (nn >= n) return;
    int g = batch[nn];
    const float* ac = g_acc + (size_t)nn * HH;
    const float* xr = g_feat + (size_t)nn * FP + HH;
    float* gs = g_gsum + (size_t)g * FP;
#pragma unroll
    for (int j = 0; j < HH; j++) atomicAdd(gs + j, ac[j]);
#pragma unroll
    for (int d = 0; d < DD; d++) atomicAdd(gs + HH + d, xr[d]);
    atomicAdd(&g_gcnt[g], 1);
}

// ---------------- 7) output MLP + sigmoid ----------------
__global__ void out_kernel(const float* __restrict__ w1,
                           const float* __restrict__ b1,
                           const float* __restrict__ w2,
                           const float* __restrict__ b2,
                           float* __restrict__ out, int gcount) {
    int g = blockIdx.x * blockDim.x + threadIdx.x;
    if (g >= gcount) return;
    float cnt = fmaxf((float)g_gcnt[g], 1.f);
    float inv = 1.f / cnt;
    float m[FF];
#pragma unroll
    for (int a = 0; a < FF; a++) m[a] = g_gsum[g * FP + a] * inv;
    float o = b2[0];
    for (int h = 0; h < HH; h++) {
        float t = b1[h];
#pragma unroll
        for (int a = 0; a < FF; a++) t = fmaf(m[a], w1[a * HH + h], t);
        o = fmaf(fmaxf(t, 0.f), w2[h], o);
    }
    out[g] = 1.f / (1.f + expf(-o));
}

// ---------------- launch ----------------
extern "C" void kernel_launch(void* const* d_in, const int* in_sizes, int n_in,
                              void* d_out, int out_size) {
    const float* x     = (const float*)d_in[0];
    const int*   ei    = (const int*)d_in[1];
    const int*   batch = (const int*)d_in[2];
    const float* gamma = (const float*)d_in[3];
    const float* beta  = (const float*)d_in[4];
    const float* in_w1 = (const float*)d_in[5];
    const float* in_b1 = (const float*)d_in[6];
    const float* in_w2 = (const float*)d_in[7];
    const float* in_b2 = (const float*)d_in[8];
    const float* cw1   = (const float*)d_in[9];
    const float* cb1   = (const float*)d_in[10];
    const float* cw2   = (const float*)d_in[11];
    const float* cb2   = (const float*)d_in[12];
    const float* ow1   = (const float*)d_in[13];
    const float* ob1   = (const float*)d_in[14];
    const float* ow2   = (const float*)d_in[15];
    const float* ob2   = (const float*)d_in[16];

    int n = in_sizes[0] / DD;
    int E = in_sizes[1] / 2;
    int G = out_size;

    zero_kernel<<<512, 256>>>(n * HH);
    bn_stats<<<148, 256>>>(x, n);
    prep_kernel<<<1, 256>>>(cw1, 1.f / (float)n);
    node_kernel<<<(n + 127) / 128, 128>>>(x, gamma, beta, in_w1, in_b1,
                                          in_w2, in_b2, n);
    edge_kernel<<<444, 128>>>(ei, cb1, cw2, cb2, E);
    pool_kernel<<<(n + 255) / 256, 256>>>(batch, n);
    out_kernel<<<1, 128>>>(ow1, ob1, ow2, ob2, (float*)d_out, G);
}

// round 3
// speedup vs baseline: 2.1458x; 2.1458x over previous
#include <cuda_runtime.h>

#define DD 13      // input feature dim
#define HH 32      // hidden dim
#define FF 45      // H + D
#define FP 48      // padded feat/weight row
#define XP 16      // padded X row
#define K1 64      // 2H (edge MLP hidden)
#define GG 128     // graphs
#define NMAX 50000

// ---------------- device scratch (no allocations allowed) ----------------
__device__ float g_sum[DD];
__device__ float g_sumsq[DD];
__device__ float g_mean[DD];
__device__ float g_istd[DD];
__device__ float g_X[NMAX * XP];        // normalized X, padded with zeros
__device__ float g_u[NMAX * K1];        // feat . Wa + b1   (per node)
__device__ float g_v[NMAX * K1];        // feat . Wb        (per node)
__device__ float g_acc[NMAX * HH];      // edge-message segment sums
__device__ float g_wc1T[K1 * FP];       // Wa = W[a]-W[45+a], k-major, padded
__device__ float g_wc2T[K1 * FP];       // Wb = W[45+a],      k-major, padded
__device__ float g_gsum[GG * FP];       // [acc(32), X(13), pad(3)] sums per graph
__device__ int   g_gcnt[GG];

__device__ __forceinline__ float tanh_fast(float x) {
    float y;
    asm("tanh.approx.f32 %0, %1;" : "=f"(y) : "f"(x));
    return y;
}

__device__ __forceinline__ void red_add_v4(float* p, float a, float b, float c, float d) {
    asm volatile("red.global.add.v4.f32 [%0], {%1, %2, %3, %4};"
                 :: "l"(p), "f"(a), "f"(b), "f"(c), "f"(d) : "memory");
}

// ---------------- 1) zero scratch ----------------
__global__ void zero_kernel(int accN) {
    int i = blockIdx.x * blockDim.x + threadIdx.x;
    int stride = gridDim.x * blockDim.x;
    for (int j = i; j < accN; j += stride) g_acc[j] = 0.f;
    if (i < DD) { g_sum[i] = 0.f; g_sumsq[i] = 0.f; }
    if (i < GG * FP) g_gsum[i] = 0.f;
    if (i < GG) g_gcnt[i] = 0;
}

// ---------------- 2) batchnorm statistics ----------------
__global__ void bn_stats(const float* __restrict__ x, int n) {
    float s[DD], s2[DD];
#pragma unroll
    for (int d = 0; d < DD; d++) { s[d] = 0.f; s2[d] = 0.f; }
    for (int i = blockIdx.x * blockDim.x + threadIdx.x; i < n;
         i += gridDim.x * blockDim.x) {
#pragma unroll
        for (int d = 0; d < DD; d++) {
            float v = x[i * DD + d];
            s[d] += v; s2[d] += v * v;
        }
    }
#pragma unroll
    for (int d = 0; d < DD; d++) {
        for (int off = 16; off > 0; off >>= 1) {
            s[d]  += __shfl_down_sync(0xffffffffu, s[d], off);
            s2[d] += __shfl_down_sync(0xffffffffu, s2[d], off);
        }
    }
    if ((threadIdx.x & 31) == 0) {
#pragma unroll
        for (int d = 0; d < DD; d++) {
            atomicAdd(&g_sum[d], s[d]);
            atomicAdd(&g_sumsq[d], s2[d]);
        }
    }
}

// ---------------- 3) finalize stats + build combined/transposed conv_w1 ----------------
__global__ void prep_kernel(const float* __restrict__ conv_w1, float invN) {
    int tid = threadIdx.x;
    if (tid < DD) {
        float mu  = g_sum[tid] * invN;
        float var = g_sumsq[tid] * invN - mu * mu;
        g_mean[tid] = mu;
        g_istd[tid] = rsqrtf(var + 1e-5f);
    }
    for (int i = tid; i < K1 * FP; i += blockDim.x) {
        int k = i / FP, a = i % FP;
        float wa = 0.f, wb = 0.f;
        if (a < FF) {
            float w0 = conv_w1[a * K1 + k];
            float w1 = conv_w1[(FF + a) * K1 + k];
            wa = w0 - w1;
            wb = w1;
        }
        g_wc1T[i] = wa;
        g_wc2T[i] = wb;
    }
}

// ---------------- 4) node kernel: BN + inputnet + per-node u/v projections ----------------
__global__ void __launch_bounds__(256)
node_kernel(const float* __restrict__ x,
            const float* __restrict__ gamma,
            const float* __restrict__ beta,
            const float* __restrict__ w1,
            const float* __restrict__ b1,
            const float* __restrict__ w2,
            const float* __restrict__ b2,
            const float* __restrict__ conv_b1,
            int n) {
    __shared__ float s_w1[DD * HH], s_w2[HH * HH], s_b1[HH], s_b2[HH];
    __shared__ float s_gam[DD], s_bet[DD], s_mu[DD], s_is[DD];
    __shared__ float s_wa[K1 * FP], s_wb[K1 * FP], s_cb1[K1];
    for (int i = threadIdx.x; i < DD * HH; i += blockDim.x) s_w1[i] = w1[i];
    for (int i = threadIdx.x; i < HH * HH; i += blockDim.x) s_w2[i] = w2[i];
    for (int i = threadIdx.x; i < K1 * FP; i += blockDim.x) {
        s_wa[i] = g_wc1T[i];
        s_wb[i] = g_wc2T[i];
    }
    if (threadIdx.x < K1) s_cb1[threadIdx.x] = conv_b1[threadIdx.x];
    if (threadIdx.x < HH) { s_b1[threadIdx.x] = b1[threadIdx.x]; s_b2[threadIdx.x] = b2[threadIdx.x]; }
    if (threadIdx.x < DD) {
        s_gam[threadIdx.x] = gamma[threadIdx.x];
        s_bet[threadIdx.x] = beta[threadIdx.x];
        s_mu[threadIdx.x]  = g_mean[threadIdx.x];
        s_is[threadIdx.x]  = g_istd[threadIdx.x];
    }
    __syncthreads();
    int nn = blockIdx.x * blockDim.x + threadIdx.x;
    if (nn >= n) return;

    // feat vector f[48] = [Hn(32), X(13), 0,0,0]
    float f[FP];
#pragma unroll
    for (int d = 0; d < DD; d++)
        f[HH + d] = (x[nn * DD + d] - s_mu[d]) * s_is[d] * s_gam[d] + s_bet[d];
    f[45] = 0.f; f[46] = 0.f; f[47] = 0.f;

    float h[HH];
#pragma unroll
    for (int j = 0; j < HH; j++) {
        float t = s_b1[j];
#pragma unroll
        for (int d = 0; d < DD; d++) t = fmaf(f[HH + d], s_w1[d * HH + j], t);
        h[j] = fmaxf(t, 0.f);
    }
#pragma unroll
    for (int j = 0; j < HH; j++) {
        float t = s_b2[j];
#pragma unroll
        for (int k = 0; k < HH; k++) t = fmaf(h[k], s_w2[k * HH + j], t);
        f[j] = tanh_fast(t);
    }

    // store padded X for pooling
    float* xp = g_X + (size_t)nn * XP;
#pragma unroll
    for (int d = 0; d < DD; d++) xp[d] = f[HH + d];
    xp[13] = 0.f; xp[14] = 0.f; xp[15] = 0.f;

    // u = f . Wa + b1c ; v = f . Wb    (k = 0..63)
    float* up = g_u + (size_t)nn * K1;
    float* vp = g_v + (size_t)nn * K1;
#pragma unroll 4
    for (int k = 0; k < K1; k++) {
        const float4* wa = (const float4*)(s_wa + k * FP);
        const float4* wb = (const float4*)(s_wb + k * FP);
        float ua = s_cb1[k], ub = 0.f, uc = 0.f, ud = 0.f;
        float va = 0.f, vb = 0.f, vc = 0.f, vd = 0.f;
#pragma unroll
        for (int q = 0; q < 12; q++) {
            float4 w = wa[q];
            ua = fmaf(f[4 * q + 0], w.x, ua);
            ub = fmaf(f[4 * q + 1], w.y, ub);
            uc = fmaf(f[4 * q + 2], w.z, uc);
            ud = fmaf(f[4 * q + 3], w.w, ud);
            w = wb[q];
            va = fmaf(f[4 * q + 0], w.x, va);
            vb = fmaf(f[4 * q + 1], w.y, vb);
            vc = fmaf(f[4 * q + 2], w.z, vc);
            vd = fmaf(f[4 * q + 3], w.w, vd);
        }
        up[k] = (ua + ub) + (uc + ud);
        vp[k] = (va + vb) + (vc + vd);
    }
}

// ---------------- 5) edge kernel (hot): h1 = relu(u[dst]+v[src]); h2 = h1.W2; scatter ----------------
__global__ void __launch_bounds__(256, 2)
edge_kernel(const int* __restrict__ ei,
            const float* __restrict__ conv_w2,
            const float* __restrict__ conv_b2,
            int E) {
    __shared__ float s_w2[K1 * HH];
    __shared__ float s_b2[HH];
    for (int i = threadIdx.x; i < K1 * HH; i += blockDim.x) s_w2[i] = conv_w2[i];
    if (threadIdx.x < HH) s_b2[threadIdx.x] = conv_b2[threadIdx.x];
    __syncthreads();

    int stride = gridDim.x * blockDim.x;
    for (int e = blockIdx.x * blockDim.x + threadIdx.x; e < E; e += stride) {
        int src = ei[e];
        int dst = ei[E + e];
        const float4* up = (const float4*)(g_u + (size_t)dst * K1);
        const float4* vp = (const float4*)(g_v + (size_t)src * K1);

        float h2[HH];
#pragma unroll
        for (int j = 0; j < HH; j++) h2[j] = s_b2[j];

#pragma unroll 1
        for (int c = 0; c < 4; c++) {
            float4 A[4], B[4];
#pragma unroll
            for (int q = 0; q < 4; q++) { A[q] = up[c * 4 + q]; B[q] = vp[c * 4 + q]; }
            float h1[16];
#pragma unroll
            for (int q = 0; q < 4; q++) {
                h1[4 * q + 0] = fmaxf(A[q].x + B[q].x, 0.f);
                h1[4 * q + 1] = fmaxf(A[q].y + B[q].y, 0.f);
                h1[4 * q + 2] = fmaxf(A[q].z + B[q].z, 0.f);
                h1[4 * q + 3] = fmaxf(A[q].w + B[q].w, 0.f);
            }
#pragma unroll
            for (int kk = 0; kk < 16; kk++) {
                float t = h1[kk];
                const float4* w2r = (const float4*)(s_w2 + (c * 16 + kk) * HH);
#pragma unroll
                for (int q = 0; q < 8; q++) {
                    float4 w = w2r[q];
                    h2[4 * q + 0] = fmaf(t, w.x, h2[4 * q + 0]);
                    h2[4 * q + 1] = fmaf(t, w.y, h2[4 * q + 1]);
                    h2[4 * q + 2] = fmaf(t, w.z, h2[4 * q + 2]);
                    h2[4 * q + 3] = fmaf(t, w.w, h2[4 * q + 3]);
                }
            }
        }
        float* ap = g_acc + (size_t)dst * HH;
#pragma unroll
        for (int q = 0; q < 8; q++) {
            float a = tanh_fast(h2[4 * q + 0]);
            float b = tanh_fast(h2[4 * q + 1]);
            float c2 = tanh_fast(h2[4 * q + 2]);
            float d = tanh_fast(h2[4 * q + 3]);
            red_add_v4(ap + 4 * q, a, b, c2, d);
        }
    }
}

// ---------------- 6) global mean pool (sums + counts) ----------------
__global__ void pool_kernel(const int* __restrict__ batch, int n) {
    int nn = blockIdx.x * blockDim.x + threadIdx.x;
    if (nn >= n) return;
    int g = batch[nn];
    const float4* ac = (const float4*)(g_acc + (size_t)nn * HH);
    const float4* xr = (const float4*)(g_X + (size_t)nn * XP);
    float* gs = g_gsum + (size_t)g * FP;
#pragma unroll
    for (int q = 0; q < 8; q++) {
        float4 v = ac[q];
        red_add_v4(gs + 4 * q, v.x, v.y, v.z, v.w);
    }
#pragma unroll
    for (int q = 0; q < 4; q++) {
        float4 v = xr[q];
        red_add_v4(gs + HH + 4 * q, v.x, v.y, v.z, v.w);
    }
    atomicAdd(&g_gcnt[g], 1);
}

// ---------------- 7) output MLP + sigmoid ----------------
__global__ void out_kernel(const float* __restrict__ w1,
                           const float* __restrict__ b1,
                           const float* __restrict__ w2,
                           const float* __restrict__ b2,
                           float* __restrict__ out, int gcount) {
    int g = blockIdx.x * blockDim.x + threadIdx.x;
    if (g >= gcount) return;
    float cnt = fmaxf((float)g_gcnt[g], 1.f);
    float inv = 1.f / cnt;
    float m[FF];
#pragma unroll
    for (int a = 0; a < FF; a++) m[a] = g_gsum[g * FP + a] * inv;
    float o = b2[0];
    for (int h = 0; h < HH; h++) {
        float t = b1[h];
#pragma unroll
        for (int a = 0; a < FF; a++) t = fmaf(m[a], w1[a * HH + h], t);
        o = fmaf(fmaxf(t, 0.f), w2[h], o);
    }
    out[g] = 1.f / (1.f + expf(-o));
}

// ---------------- launch ----------------
extern "C" void kernel_launch(void* const* d_in, const int* in_sizes, int n_in,
                              void* d_out, int out_size) {
    const float* x     = (const float*)d_in[0];
    const int*   ei    = (const int*)d_in[1];
    const int*   batch = (const int*)d_in[2];
    const float* gamma = (const float*)d_in[3];
    const float* beta  = (const float*)d_in[4];
    const float* in_w1 = (const float*)d_in[5];
    const float* in_b1 = (const float*)d_in[6];
    const float* in_w2 = (const float*)d_in[7];
    const float* in_b2 = (const float*)d_in[8];
    const float* cw1   = (const float*)d_in[9];
    const float* cb1   = (const float*)d_in[10];
    const float* cw2   = (const float*)d_in[11];
    const float* cb2   = (const float*)d_in[12];
    const float* ow1   = (const float*)d_in[13];
    const float* ob1   = (const float*)d_in[14];
    const float* ow2   = (const float*)d_in[15];
    const float* ob2   = (const float*)d_in[16];

    int n = in_sizes[0] / DD;
    int E = in_sizes[1] / 2;
    int G = out_size;

    zero_kernel<<<512, 256>>>(n * HH);
    bn_stats<<<148, 256>>>(x, n);
    prep_kernel<<<1, 256>>>(cw1, 1.f / (float)n);
    node_kernel<<<(n + 255) / 256, 256>>>(x, gamma, beta, in_w1, in_b1,
                                          in_w2, in_b2, cb1, n);
    edge_kernel<<<592, 256>>>(ei, cw2, cb2, E);
    pool_kernel<<<(n + 255) / 256, 256>>>(batch, n);
    out_kernel<<<1, 128>>>(ow1, ob1, ow2, ob2, (float*)d_out, G);
}

// round 4
// speedup vs baseline: 2.7471x; 1.2802x over previous
#include <cuda_runtime.h>

#define DD 13      // input feature dim
#define HH 32      // hidden dim
#define FF 45      // H + D
#define XP 16      // padded X row
#define K1 64      // 2H (edge MLP hidden)
#define GG 128     // graphs
#define NMAX 50000
#define AP 45      // pairs per wab row (a index 0..44)
#define WABROW 92  // floats per wab row (46 pairs, last zero-padded)

typedef unsigned long long ull;

// ---------------- device scratch (no allocations allowed) ----------------
__device__ float g_sum[DD];
__device__ float g_sumsq[DD];
__device__ float g_mean[DD];
__device__ float g_istd[DD];
__device__ float g_X[NMAX * XP];        // normalized X, padded with zeros
__device__ float g_u[NMAX * K1];        // feat . Wa + b1   (per node)
__device__ float g_v[NMAX * K1];        // feat . Wb        (per node)
__device__ float g_acc[NMAX * HH];      // edge-message segment sums
__device__ float g_wab[K1 * WABROW];    // interleaved (Wa,Wb) pairs, k-major
__device__ float g_gsum[GG * (HH + XP)];
__device__ int   g_gcnt[GG];

__device__ __forceinline__ float tanh_fast(float x) {
    float y;
    asm("tanh.approx.f32 %0, %1;" : "=f"(y) : "f"(x));
    return y;
}
__device__ __forceinline__ void red_add_v4(float* p, float a, float b, float c, float d) {
    asm volatile("red.global.add.v4.f32 [%0], {%1, %2, %3, %4};"
                 :: "l"(p), "f"(a), "f"(b), "f"(c), "f"(d) : "memory");
}
__device__ __forceinline__ ull pack2(float x) {
    ull r;
    asm("mov.b64 %0, {%1, %1};" : "=l"(r) : "r"(__float_as_uint(x)));
    return r;
}
__device__ __forceinline__ void ffma2(ull& d, ull a, ull b) {
    asm("fma.rn.f32x2 %0, %1, %2, %0;" : "+l"(d) : "l"(a), "l"(b));
}
__device__ __forceinline__ ull add2(ull a, ull b) {
    ull r;
    asm("add.rn.f32x2 %0, %1, %2;" : "=l"(r) : "l"(a), "l"(b));
    return r;
}
__device__ __forceinline__ void unpack2(ull v, float& lo, float& hi) {
    unsigned int a, b;
    asm("mov.b64 {%0, %1}, %2;" : "=r"(a), "=r"(b) : "l"(v));
    lo = __uint_as_float(a);
    hi = __uint_as_float(b);
}

// ---------------- 1) zero scratch ----------------
__global__ void zero_kernel(int accN) {
    int i = blockIdx.x * blockDim.x + threadIdx.x;
    int stride = gridDim.x * blockDim.x;
    for (int j = i; j < accN; j += stride) g_acc[j] = 0.f;
    if (i < DD) { g_sum[i] = 0.f; g_sumsq[i] = 0.f; }
    if (i < GG * (HH + XP)) g_gsum[i] = 0.f;
    if (i < GG) g_gcnt[i] = 0;
}

// ---------------- 2) batchnorm statistics ----------------
__global__ void bn_stats(const float* __restrict__ x, int n) {
    float s[DD], s2[DD];
#pragma unroll
    for (int d = 0; d < DD; d++) { s[d] = 0.f; s2[d] = 0.f; }
    for (int i = blockIdx.x * blockDim.x + threadIdx.x; i < n;
         i += gridDim.x * blockDim.x) {
#pragma unroll
        for (int d = 0; d < DD; d++) {
            float v = x[i * DD + d];
            s[d] += v; s2[d] += v * v;
        }
    }
#pragma unroll
    for (int d = 0; d < DD; d++) {
        for (int off = 16; off > 0; off >>= 1) {
            s[d]  += __shfl_down_sync(0xffffffffu, s[d], off);
            s2[d] += __shfl_down_sync(0xffffffffu, s2[d], off);
        }
    }
    if ((threadIdx.x & 31) == 0) {
#pragma unroll
        for (int d = 0; d < DD; d++) {
            atomicAdd(&g_sum[d], s[d]);
            atomicAdd(&g_sumsq[d], s2[d]);
        }
    }
}

// ---------------- 3) finalize stats + interleaved combined conv_w1 ----------------
// wab[k][2a]   = W[a][k] - W[45+a][k]   (xi coefficient)
// wab[k][2a+1] = W[45+a][k]             (xj coefficient)
__global__ void prep_kernel(const float* __restrict__ conv_w1, float invN) {
    int tid = threadIdx.x;
    if (tid < DD) {
        float mu  = g_sum[tid] * invN;
        float var = g_sumsq[tid] * invN - mu * mu;
        g_mean[tid] = mu;
        g_istd[tid] = rsqrtf(var + 1e-5f);
    }
    for (int i = tid; i < K1 * (WABROW / 2); i += blockDim.x) {
        int k = i / (WABROW / 2), a = i % (WABROW / 2);
        float wa = 0.f, wb = 0.f;
        if (a < FF) {
            float w0 = conv_w1[a * K1 + k];
            float w1 = conv_w1[(FF + a) * K1 + k];
            wa = w0 - w1;
            wb = w1;
        }
        g_wab[k * WABROW + 2 * a]     = wa;
        g_wab[k * WABROW + 2 * a + 1] = wb;
    }
}

// ---------------- 4) node kernel: BN + inputnet + packed u/v projection ----------------
__global__ void node_kernel(const float* __restrict__ x,
                            const float* __restrict__ gamma,
                            const float* __restrict__ beta,
                            const float* __restrict__ w1,
                            const float* __restrict__ b1,
                            const float* __restrict__ w2,
                            const float* __restrict__ b2,
                            const float* __restrict__ conv_b1,
                            int n) {
    __shared__ float s_w1[DD * HH], s_w2[HH * HH], s_b1[HH], s_b2[HH];
    __shared__ float s_gam[DD], s_bet[DD], s_mu[DD], s_is[DD];
    __shared__ float s_wab[K1 * WABROW];
    __shared__ ull   s_cbp[K1];           // (conv_b1[k], 0) packed
    for (int i = threadIdx.x; i < DD * HH; i += blockDim.x) s_w1[i] = w1[i];
    for (int i = threadIdx.x; i < HH * HH; i += blockDim.x) s_w2[i] = w2[i];
    for (int i = threadIdx.x; i < K1 * WABROW; i += blockDim.x) s_wab[i] = g_wab[i];
    if (threadIdx.x < K1)
        s_cbp[threadIdx.x] = (ull)__float_as_uint(conv_b1[threadIdx.x]);
    if (threadIdx.x < HH) { s_b1[threadIdx.x] = b1[threadIdx.x]; s_b2[threadIdx.x] = b2[threadIdx.x]; }
    if (threadIdx.x < DD) {
        s_gam[threadIdx.x] = gamma[threadIdx.x];
        s_bet[threadIdx.x] = beta[threadIdx.x];
        s_mu[threadIdx.x]  = g_mean[threadIdx.x];
        s_is[threadIdx.x]  = g_istd[threadIdx.x];
    }
    __syncthreads();
    int nn = blockIdx.x * blockDim.x + threadIdx.x;
    if (nn >= n) return;

    float X[DD];
#pragma unroll
    for (int d = 0; d < DD; d++)
        X[d] = (x[nn * DD + d] - s_mu[d]) * s_is[d] * s_gam[d] + s_bet[d];

    float h[HH];
#pragma unroll
    for (int j = 0; j < HH; j++) {
        float t = s_b1[j];
#pragma unroll
        for (int d = 0; d < DD; d++) t = fmaf(X[d], s_w1[d * HH + j], t);
        h[j] = fmaxf(t, 0.f);
    }

    // fp[a] = (f[a], f[a]) packed; f = [tanh outputs(32), X(13)]
    ull fp[FF];
#pragma unroll
    for (int j = 0; j < HH; j++) {
        float t = s_b2[j];
#pragma unroll
        for (int k = 0; k < HH; k++) t = fmaf(h[k], s_w2[k * HH + j], t);
        fp[j] = pack2(tanh_fast(t));
    }
#pragma unroll
    for (int d = 0; d < DD; d++) fp[HH + d] = pack2(X[d]);

    // store padded X for pooling
    float* xp = g_X + (size_t)nn * XP;
#pragma unroll
    for (int d = 0; d < DD; d++) xp[d] = X[d];
    xp[13] = 0.f; xp[14] = 0.f; xp[15] = 0.f;

    // (u[k], v[k]) = sum_a f[a] * (wa, wb)  + (b1c[k], 0)
    float* up = g_u + (size_t)nn * K1;
    float* vp = g_v + (size_t)nn * K1;
#pragma unroll 1
    for (int k4 = 0; k4 < K1 / 4; k4++) {
        float uu[4], vv[4];
#pragma unroll
        for (int j = 0; j < 4; j++) {
            int k = 4 * k4 + j;
            ull a0 = s_cbp[k], a1 = 0ULL;
            const ulonglong2* wr = (const ulonglong2*)(s_wab + k * WABROW);
#pragma unroll
            for (int q = 0; q < 22; q++) {
                ulonglong2 w = wr[q];
                ffma2(a0, fp[2 * q], w.x);
                ffma2(a1, fp[2 * q + 1], w.y);
            }
            ull wl = ((const ull*)(s_wab + k * WABROW))[44];
            ffma2(a0, fp[44], wl);
            unpack2(add2(a0, a1), uu[j], vv[j]);
        }
        *(float4*)(up + 4 * k4) = make_float4(uu[0], uu[1], uu[2], uu[3]);
        *(float4*)(vp + 4 * k4) = make_float4(vv[0], vv[1], vv[2], vv[3]);
    }
}

// ---------------- 5) edge kernel (hot): 2 edges/thread, f32x2 GEMM ----------------
__global__ void __launch_bounds__(128, 3)
edge_kernel(const int* __restrict__ ei,
            const float* __restrict__ conv_w2,
            const float* __restrict__ conv_b2,
            int E) {
    __shared__ float s_w2[K1 * HH];
    __shared__ ull   s_b2p[HH / 2];
    for (int i = threadIdx.x; i < K1 * HH; i += blockDim.x) s_w2[i] = conv_w2[i];
    if (threadIdx.x < HH / 2)
        s_b2p[threadIdx.x] = ((const ull*)conv_b2)[threadIdx.x];
    __syncthreads();

    int nPairs = (E + 1) >> 1;
    int stride = gridDim.x * blockDim.x;
    for (int p = blockIdx.x * blockDim.x + threadIdx.x; p < nPairs; p += stride) {
        int e0 = 2 * p, e1 = 2 * p + 1;
        bool has1 = e1 < E;
        int src0 = ei[e0];
        int dst0 = ei[E + e0];
        int src1 = has1 ? ei[e1] : src0;
        int dst1 = has1 ? ei[E + e1] : dst0;

        const float4* u0 = (const float4*)(g_u + (size_t)dst0 * K1);
        const float4* v0 = (const float4*)(g_v + (size_t)src0 * K1);
        const float4* u1 = (const float4*)(g_u + (size_t)dst1 * K1);
        const float4* v1 = (const float4*)(g_v + (size_t)src1 * K1);

        ull h2a[16], h2b[16];
#pragma unroll
        for (int q = 0; q < 16; q++) { h2a[q] = s_b2p[q]; h2b[q] = s_b2p[q]; }

#pragma unroll 1
        for (int c = 0; c < 4; c++) {
            float h10[16], h11[16];
#pragma unroll
            for (int q = 0; q < 4; q++) {
                float4 A = u0[c * 4 + q], B = v0[c * 4 + q];
                h10[4 * q + 0] = fmaxf(A.x + B.x, 0.f);
                h10[4 * q + 1] = fmaxf(A.y + B.y, 0.f);
                h10[4 * q + 2] = fmaxf(A.z + B.z, 0.f);
                h10[4 * q + 3] = fmaxf(A.w + B.w, 0.f);
            }
#pragma unroll
            for (int q = 0; q < 4; q++) {
                float4 A = u1[c * 4 + q], B = v1[c * 4 + q];
                h11[4 * q + 0] = fmaxf(A.x + B.x, 0.f);
                h11[4 * q + 1] = fmaxf(A.y + B.y, 0.f);
                h11[4 * q + 2] = fmaxf(A.z + B.z, 0.f);
                h11[4 * q + 3] = fmaxf(A.w + B.w, 0.f);
            }
#pragma unroll
            for (int kk = 0; kk < 16; kk++) {
                int k = c * 16 + kk;
                ull t0 = pack2(h10[kk]);
                ull t1 = pack2(h11[kk]);
                const ulonglong2* wr = (const ulonglong2*)(s_w2 + (k << 5));
#pragma unroll
                for (int q = 0; q < 8; q++) {
                    ulonglong2 w = wr[q];
                    ffma2(h2a[2 * q],     t0, w.x);
                    ffma2(h2a[2 * q + 1], t0, w.y);
                    ffma2(h2b[2 * q],     t1, w.x);
                    ffma2(h2b[2 * q + 1], t1, w.y);
                }
            }
        }

        {
            float* ap = g_acc + (size_t)dst0 * HH;
#pragma unroll
            for (int q = 0; q < 8; q++) {
                float a, b, c2, d;
                unpack2(h2a[2 * q], a, b);
                unpack2(h2a[2 * q + 1], c2, d);
                red_add_v4(ap + 4 * q, tanh_fast(a), tanh_fast(b),
                           tanh_fast(c2), tanh_fast(d));
            }
        }
        if (has1) {
            float* ap = g_acc + (size_t)dst1 * HH;
#pragma unroll
            for (int q = 0; q < 8; q++) {
                float a, b, c2, d;
                unpack2(h2b[2 * q], a, b);
                unpack2(h2b[2 * q + 1], c2, d);
                red_add_v4(ap + 4 * q, tanh_fast(a), tanh_fast(b),
                           tanh_fast(c2), tanh_fast(d));
            }
        }
    }
}

// ---------------- 6) global mean pool (sums + counts) ----------------
__global__ void pool_kernel(const int* __restrict__ batch, int n) {
    int nn = blockIdx.x * blockDim.x + threadIdx.x;
    if (nn >= n) return;
    int g = batch[nn];
    const float4* ac = (const float4*)(g_acc + (size_t)nn * HH);
    const float4* xr = (const float4*)(g_X + (size_t)nn * XP);
    float* gs = g_gsum + (size_t)g * (HH + XP);
#pragma unroll
    for (int q = 0; q < 8; q++) {
        float4 v = ac[q];
        red_add_v4(gs + 4 * q, v.x, v.y, v.z, v.w);
    }
#pragma unroll
    for (int q = 0; q < 4; q++) {
        float4 v = xr[q];
        red_add_v4(gs + HH + 4 * q, v.x, v.y, v.z, v.w);
    }
    atomicAdd(&g_gcnt[g], 1);
}

// ---------------- 7) output MLP + sigmoid ----------------
__global__ void out_kernel(const float* __restrict__ w1,
                           const float* __restrict__ b1,
                           const float* __restrict__ w2,
                           const float* __restrict__ b2,
                           float* __restrict__ out, int gcount) {
    int g = blockIdx.x * blockDim.x + threadIdx.x;
    if (g >= gcount) return;
    float cnt = fmaxf((float)g_gcnt[g], 1.f);
    float inv = 1.f / cnt;
    float m[FF];
#pragma unroll
    for (int a = 0; a < FF; a++) m[a] = g_gsum[g * (HH + XP) + a] * inv;
    float o = b2[0];
    for (int h = 0; h < HH; h++) {
        float t = b1[h];
#pragma unroll
        for (int a = 0; a < FF; a++) t = fmaf(m[a], w1[a * HH + h], t);
        o = fmaf(fmaxf(t, 0.f), w2[h], o);
    }
    out[g] = 1.f / (1.f + expf(-o));
}

// ---------------- launch ----------------
extern "C" void kernel_launch(void* const* d_in, const int* in_sizes, int n_in,
                              void* d_out, int out_size) {
    const float* x     = (const float*)d_in[0];
    const int*   ei    = (const int*)d_in[1];
    const int*   batch = (const int*)d_in[2];
    const float* gamma = (const float*)d_in[3];
    const float* beta  = (const float*)d_in[4];
    const float* in_w1 = (const float*)d_in[5];
    const float* in_b1 = (const float*)d_in[6];
    const float* in_w2 = (const float*)d_in[7];
    const float* in_b2 = (const float*)d_in[8];
    const float* cw1   = (const float*)d_in[9];
    const float* cb1   = (const float*)d_in[10];
    const float* cw2   = (const float*)d_in[11];
    const float* cb2   = (const float*)d_in[12];
    const float* ow1   = (const float*)d_in[13];
    const float* ob1   = (const float*)d_in[14];
    const float* ow2   = (const float*)d_in[15];
    const float* ob2   = (const float*)d_in[16];

    int n = in_sizes[0] / DD;
    int E = in_sizes[1] / 2;
    int G = out_size;

    zero_kernel<<<512, 256>>>(n * HH);
    bn_stats<<<148, 256>>>(x, n);
    prep_kernel<<<1, 256>>>(cw1, 1.f / (float)n);
    node_kernel<<<(n + 127) / 128, 128>>>(x, gamma, beta, in_w1, in_b1,
                                          in_w2, in_b2, cb1, n);
    edge_kernel<<<444, 128>>>(ei, cw2, cb2, E);
    pool_kernel<<<(n + 255) / 256, 256>>>(batch, n);
    out_kernel<<<1, 128>>>(ow1, ob1, ow2, ob2, (float*)d_out, G);
}

// round 6
// speedup vs baseline: 2.9171x; 1.0619x over previous
#include <cuda_runtime.h>

#define DD 13
#define HH 32
#define FF 45
#define XP 16
#define K1 64
#define GG 128
#define NMAX 50000
#define WABROW 92
#define TILE 128
#define H1STRIDE 68   // floats per staged h1 row (64 + 4 pad for bank spread)

typedef unsigned long long ull;
typedef unsigned int u32;

// ---------------- device scratch ----------------
__device__ float g_sum[DD];
__device__ float g_sumsq[DD];
__device__ float g_mean[DD];
__device__ float g_istd[DD];
__device__ float g_X[NMAX * XP];
__device__ float g_u[NMAX * K1];
__device__ float g_v[NMAX * K1];
__device__ float g_acc[NMAX * HH];
__device__ float g_wab[K1 * WABROW];
__device__ float g_gsum[GG * (HH + XP)];
__device__ int   g_gcnt[GG];

// ---------------- helpers ----------------
__device__ __forceinline__ float tanh_fast(float x) {
    float y; asm("tanh.approx.f32 %0, %1;" : "=f"(y) : "f"(x)); return y;
}
__device__ __forceinline__ void red_add_v4(float* p, float a, float b, float c, float d) {
    asm volatile("red.global.add.v4.f32 [%0], {%1, %2, %3, %4};"
                 :: "l"(p), "f"(a), "f"(b), "f"(c), "f"(d) : "memory");
}
__device__ __forceinline__ ull pack2(float x) {
    ull r; asm("mov.b64 %0, {%1, %1};" : "=l"(r) : "r"(__float_as_uint(x))); return r;
}
__device__ __forceinline__ void ffma2(ull& d, ull a, ull b) {
    asm("fma.rn.f32x2 %0, %1, %2, %0;" : "+l"(d) : "l"(a), "l"(b));
}
__device__ __forceinline__ ull add2(ull a, ull b) {
    ull r; asm("add.rn.f32x2 %0, %1, %2;" : "=l"(r) : "l"(a), "l"(b)); return r;
}
__device__ __forceinline__ void unpack2(ull v, float& lo, float& hi) {
    u32 a, b; asm("mov.b64 {%0, %1}, %2;" : "=r"(a), "=r"(b) : "l"(v));
    lo = __uint_as_float(a); hi = __uint_as_float(b);
}

// ---------------- 1) small zero ----------------
__global__ void zero_kernel() {
    int i = threadIdx.x;
    if (i < DD) { g_sum[i] = 0.f; g_sumsq[i] = 0.f; }
    for (int j = i; j < GG * (HH + XP); j += blockDim.x) g_gsum[j] = 0.f;
    if (i < GG) g_gcnt[i] = 0;
}

// ---------------- 2) batchnorm statistics ----------------
__global__ void bn_stats(const float* __restrict__ x, int n) {
    float s[DD], s2[DD];
#pragma unroll
    for (int d = 0; d < DD; d++) { s[d] = 0.f; s2[d] = 0.f; }
    for (int i = blockIdx.x * blockDim.x + threadIdx.x; i < n;
         i += gridDim.x * blockDim.x) {
#pragma unroll
        for (int d = 0; d < DD; d++) {
            float v = x[i * DD + d];
            s[d] += v; s2[d] += v * v;
        }
    }
#pragma unroll
    for (int d = 0; d < DD; d++) {
        for (int off = 16; off > 0; off >>= 1) {
            s[d]  += __shfl_down_sync(0xffffffffu, s[d], off);
            s2[d] += __shfl_down_sync(0xffffffffu, s2[d], off);
        }
    }
    if ((threadIdx.x & 31) == 0) {
#pragma unroll
        for (int d = 0; d < DD; d++) {
            atomicAdd(&g_sum[d], s[d]);
            atomicAdd(&g_sumsq[d], s2[d]);
        }
    }
}

// ---------------- 3) prep: stats + interleaved combined conv_w1 ----------------
__global__ void prep_kernel(const float* __restrict__ conv_w1, float invN) {
    int tid = threadIdx.x;
    if (tid < DD) {
        float mu  = g_sum[tid] * invN;
        float var = g_sumsq[tid] * invN - mu * mu;
        g_mean[tid] = mu;
        g_istd[tid] = rsqrtf(var + 1e-5f);
    }
    for (int i = tid; i < K1 * (WABROW / 2); i += blockDim.x) {
        int k = i / (WABROW / 2), a = i % (WABROW / 2);
        float wa = 0.f, wb = 0.f;
        if (a < FF) {
            float w0 = conv_w1[a * K1 + k];
            float w1 = conv_w1[(FF + a) * K1 + k];
            wa = w0 - w1; wb = w1;
        }
        g_wab[k * WABROW + 2 * a]     = wa;
        g_wab[k * WABROW + 2 * a + 1] = wb;
    }
}

// ---------------- 4) node kernel: BN + inputnet + packed u/v + zero acc ----------------
__global__ void node_kernel(const float* __restrict__ x,
                            const float* __restrict__ gamma,
                            const float* __restrict__ beta,
                            const float* __restrict__ w1,
                            const float* __restrict__ b1,
                            const float* __restrict__ w2,
                            const float* __restrict__ b2,
                            const float* __restrict__ conv_b1,
                            int n) {
    __shared__ float s_w1[DD * HH], s_w2[HH * HH], s_b1[HH], s_b2[HH];
    __shared__ float s_gam[DD], s_bet[DD], s_mu[DD], s_is[DD];
    __shared__ float s_wab[K1 * WABROW];
    __shared__ ull   s_cbp[K1];
    for (int i = threadIdx.x; i < DD * HH; i += blockDim.x) s_w1[i] = w1[i];
    for (int i = threadIdx.x; i < HH * HH; i += blockDim.x) s_w2[i] = w2[i];
    for (int i = threadIdx.x; i < K1 * WABROW; i += blockDim.x) s_wab[i] = g_wab[i];
    if (threadIdx.x < K1)
        s_cbp[threadIdx.x] = (ull)__float_as_uint(conv_b1[threadIdx.x]);
    if (threadIdx.x < HH) { s_b1[threadIdx.x] = b1[threadIdx.x]; s_b2[threadIdx.x] = b2[threadIdx.x]; }
    if (threadIdx.x < DD) {
        s_gam[threadIdx.x] = gamma[threadIdx.x];
        s_bet[threadIdx.x] = beta[threadIdx.x];
        s_mu[threadIdx.x]  = g_mean[threadIdx.x];
        s_is[threadIdx.x]  = g_istd[threadIdx.x];
    }
    __syncthreads();
    int nn = blockIdx.x * blockDim.x + threadIdx.x;
    if (nn >= n) return;

    float X[DD];
#pragma unroll
    for (int d = 0; d < DD; d++)
        X[d] = (x[nn * DD + d] - s_mu[d]) * s_is[d] * s_gam[d] + s_bet[d];

    float h[HH];
#pragma unroll
    for (int j = 0; j < HH; j++) {
        float t = s_b1[j];
#pragma unroll
        for (int d = 0; d < DD; d++) t = fmaf(X[d], s_w1[d * HH + j], t);
        h[j] = fmaxf(t, 0.f);
    }
    ull fp[FF];
#pragma unroll
    for (int j = 0; j < HH; j++) {
        float t = s_b2[j];
#pragma unroll
        for (int k = 0; k < HH; k++) t = fmaf(h[k], s_w2[k * HH + j], t);
        fp[j] = pack2(tanh_fast(t));
    }
#pragma unroll
    for (int d = 0; d < DD; d++) fp[HH + d] = pack2(X[d]);

    float* xp = g_X + (size_t)nn * XP;
#pragma unroll
    for (int d = 0; d < DD; d++) xp[d] = X[d];
    xp[13] = 0.f; xp[14] = 0.f; xp[15] = 0.f;

    // zero this node's accumulator row
    float4 z = make_float4(0.f, 0.f, 0.f, 0.f);
    float4* ar = (float4*)(g_acc + (size_t)nn * HH);
#pragma unroll
    for (int q = 0; q < 8; q++) ar[q] = z;

    float* up = g_u + (size_t)nn * K1;
    float* vp = g_v + (size_t)nn * K1;
#pragma unroll 1
    for (int k4 = 0; k4 < K1 / 4; k4++) {
        float uu[4], vv[4];
#pragma unroll
        for (int j = 0; j < 4; j++) {
            int k = 4 * k4 + j;
            ull a0 = s_cbp[k], a1 = 0ULL;
            const ulonglong2* wr = (const ulonglong2*)(s_wab + k * WABROW);
#pragma unroll
            for (int q = 0; q < 22; q++) {
                ulonglong2 w = wr[q];
                ffma2(a0, fp[2 * q], w.x);
                ffma2(a1, fp[2 * q + 1], w.y);
            }
            ull wl = ((const ull*)(s_wab + k * WABROW))[44];
            ffma2(a0, fp[44], wl);
            unpack2(add2(a0, a1), uu[j], vv[j]);
        }
        *(float4*)(up + 4 * k4) = make_float4(uu[0], uu[1], uu[2], uu[3]);
        *(float4*)(vp + 4 * k4) = make_float4(vv[0], vv[1], vv[2], vv[3]);
    }
}

// ---------------- 5) edge kernel: staged coalesced gather + FFMA2 GEMM ----------------
__global__ void __launch_bounds__(128, 5)
edge_kernel(const int* __restrict__ ei,
            const float* __restrict__ conv_w2,
            const float* __restrict__ conv_b2,
            int E, int ntiles) {
    __shared__ float s_h1[TILE * H1STRIDE];   // 34816 B
    __shared__ float s_w2[K1 * HH];           // 8192 B
    __shared__ ull   s_b2p[HH / 2];

    int tid = threadIdx.x;
    int wid = tid >> 5, lid = tid & 31;
    for (int i = tid; i < K1 * HH; i += 128) s_w2[i] = conv_w2[i];
    if (tid < HH / 2) s_b2p[tid] = ((const ull*)conv_b2)[tid];
    __syncthreads();

    int c4 = lid & 15;       // quad index within a row
    int hi16 = lid >> 4;     // which of the 2 rows this lane serves

    for (int tile = blockIdx.x; tile < ntiles; tile += gridDim.x) {
        int base = tile * TILE;
        int e = base + tid;
        bool val = e < E;
        int msrc = val ? ei[e] : 0;
        int mdst = val ? ei[E + e] : 0;

        // ---- stage h1 = relu(u[dst]+v[src]) for this warp's 32 rows ----
#pragma unroll 4
        for (int s = 0; s < 16; s++) {
            int rl = 2 * s + hi16;                 // row within warp (0..31)
            int dn = __shfl_sync(0xffffffffu, mdst, rl);
            int sn = __shfl_sync(0xffffffffu, msrc, rl);
            float4 U = ((const float4*)(g_u + (size_t)dn * K1))[c4];
            float4 V = ((const float4*)(g_v + (size_t)sn * K1))[c4];
            float4 o;
            o.x = fmaxf(U.x + V.x, 0.f);
            o.y = fmaxf(U.y + V.y, 0.f);
            o.z = fmaxf(U.z + V.z, 0.f);
            o.w = fmaxf(U.w + V.w, 0.f);
            int row = (wid << 5) + rl;             // row within tile (0..127)
            *(float4*)(s_h1 + row * H1STRIDE + 4 * c4) = o;
        }
        __syncthreads();

        // ---- compute: 64x32 layer for this thread's edge ----
        ull h2[16];
#pragma unroll
        for (int q = 0; q < 16; q++) h2[q] = s_b2p[q];

        const float* hrow = s_h1 + tid * H1STRIDE;
#pragma unroll 2
        for (int q = 0; q < 16; q++) {
            float4 hq = *(const float4*)(hrow + 4 * q);
#pragma unroll
            for (int j = 0; j < 4; j++) {
                int k = 4 * q + j;
                float t = (j == 0) ? hq.x : (j == 1) ? hq.y : (j == 2) ? hq.z : hq.w;
                ull tp = pack2(t);
                const ulonglong2* wr = (const ulonglong2*)(s_w2 + (k << 5));
#pragma unroll
                for (int i = 0; i < 8; i++) {
                    ulonglong2 w = wr[i];
                    ffma2(h2[2 * i],     tp, w.x);
                    ffma2(h2[2 * i + 1], tp, w.y);
                }
            }
        }

        if (val) {
            float* ap = g_acc + (size_t)mdst * HH;
#pragma unroll
            for (int q = 0; q < 8; q++) {
                float a, b, c, d;
                unpack2(h2[2 * q], a, b);
                unpack2(h2[2 * q + 1], c, d);
                red_add_v4(ap + 4 * q, tanh_fast(a), tanh_fast(b),
                           tanh_fast(c), tanh_fast(d));
            }
        }
        __syncthreads();
    }
}

// ---------------- 6) global mean pool ----------------
__global__ void pool_kernel(const int* __restrict__ batch, int n) {
    int nn = blockIdx.x * blockDim.x + threadIdx.x;
    if (nn >= n) return;
    int g = batch[nn];
    const float4* ac = (const float4*)(g_acc + (size_t)nn * HH);
    const float4* xr = (const float4*)(g_X + (size_t)nn * XP);
    float* gs = g_gsum + (size_t)g * (HH + XP);
#pragma unroll
    for (int q = 0; q < 8; q++) {
        float4 v = ac[q];
        red_add_v4(gs + 4 * q, v.x, v.y, v.z, v.w);
    }
#pragma unroll
    for (int q = 0; q < 4; q++) {
        float4 v = xr[q];
        red_add_v4(gs + HH + 4 * q, v.x, v.y, v.z, v.w);
    }
    atomicAdd(&g_gcnt[g], 1);
}

// ---------------- 7) output MLP + sigmoid ----------------
__global__ void out_kernel(const float* __restrict__ w1,
                           const float* __restrict__ b1,
                           const float* __restrict__ w2,
                           const float* __restrict__ b2,
                           float* __restrict__ out, int gcount) {
    int g = blockIdx.x * blockDim.x + threadIdx.x;
    if (g >= gcount) return;
    float cnt = fmaxf((float)g_gcnt[g], 1.f);
    float inv = 1.f / cnt;
    float m[FF];
#pragma unroll
    for (int a = 0; a < FF; a++) m[a] = g_gsum[g * (HH + XP) + a] * inv;
    float o = b2[0];
    for (int h = 0; h < HH; h++) {
        float t = b1[h];
#pragma unroll
        for (int a = 0; a < FF; a++) t = fmaf(m[a], w1[a * HH + h], t);
        o = fmaf(fmaxf(t, 0.f), w2[h], o);
    }
    out[g] = 1.f / (1.f + expf(-o));
}

// ---------------- launch ----------------
extern "C" void kernel_launch(void* const* d_in, const int* in_sizes, int n_in,
                              void* d_out, int out_size) {
    const float* x     = (const float*)d_in[0];
    const int*   ei    = (const int*)d_in[1];
    const int*   batch = (const int*)d_in[2];
    const float* gamma = (const float*)d_in[3];
    const float* beta  = (const float*)d_in[4];
    const float* in_w1 = (const float*)d_in[5];
    const float* in_b1 = (const float*)d_in[6];
    const float* in_w2 = (const float*)d_in[7];
    const float* in_b2 = (const float*)d_in[8];
    const float* cw1   = (const float*)d_in[9];
    const float* cb1   = (const float*)d_in[10];
    const float* cw2   = (const float*)d_in[11];
    const float* cb2   = (const float*)d_in[12];
    const float* ow1   = (const float*)d_in[13];
    const float* ob1   = (const float*)d_in[14];
    const float* ow2   = (const float*)d_in[15];
    const float* ob2   = (const float*)d_in[16];

    int n = in_sizes[0] / DD;
    int E = in_sizes[1] / 2;
    int G = out_size;
    int ntiles = (E + TILE - 1) / TILE;
    int grid = 740;
    if (grid > ntiles) grid = ntiles;

    zero_kernel<<<1, 256>>>();
    bn_stats<<<148, 256>>>(x, n);
    prep_kernel<<<1, 256>>>(cw1, 1.f / (float)n);
    node_kernel<<<(n + 127) / 128, 128>>>(x, gamma, beta, in_w1, in_b1,
                                          in_w2, in_b2, cb1, n);
    edge_kernel<<<grid, 128>>>(ei, cw2, cb2, E, ntiles);
    pool_kernel<<<(n + 255) / 256, 256>>>(batch, n);
    out_kernel<<<1, 128>>>(ow1, ob1, ow2, ob2, (float*)d_out, G);
}

// round 7
// speedup vs baseline: 2.9782x; 1.0209x over previous
#include <cuda_runtime.h>

#define DD 13
#define HH 32
#define FF 45
#define XP 16
#define K1 64
#define GG 128
#define NMAX 50000
#define WABROW 92
#define TILE 128
#define H1STRIDE 68   // floats per staged h1 row; 68%32==4 -> conflict-free LDS.128

typedef unsigned long long ull;
typedef unsigned int u32;

// ---------------- device scratch ----------------
__device__ float g_sum[DD];
__device__ float g_sumsq[DD];
__device__ float g_mean[DD];
__device__ float g_istd[DD];
__device__ float g_X[NMAX * XP];
__device__ float g_u[NMAX * K1];
__device__ float g_v[NMAX * K1];
__device__ float g_acc[NMAX * HH];
__device__ float g_wab[K1 * WABROW];
__device__ float g_gsum[GG * (HH + XP)];
__device__ int   g_gcnt[GG];

// ---------------- helpers ----------------
__device__ __forceinline__ float tanh_fast(float x) {
    float y; asm("tanh.approx.f32 %0, %1;" : "=f"(y) : "f"(x)); return y;
}
__device__ __forceinline__ void red_add_v4(float* p, float a, float b, float c, float d) {
    asm volatile("red.global.add.v4.f32 [%0], {%1, %2, %3, %4};"
                 :: "l"(p), "f"(a), "f"(b), "f"(c), "f"(d) : "memory");
}
__device__ __forceinline__ ull pack2(float x) {
    ull r; asm("mov.b64 %0, {%1, %1};" : "=l"(r) : "r"(__float_as_uint(x))); return r;
}
__device__ __forceinline__ void ffma2(ull& d, ull a, ull b) {
    asm("fma.rn.f32x2 %0, %1, %2, %0;" : "+l"(d) : "l"(a), "l"(b));
}
__device__ __forceinline__ ull add2(ull a, ull b) {
    ull r; asm("add.rn.f32x2 %0, %1, %2;" : "=l"(r) : "l"(a), "l"(b)); return r;
}
__device__ __forceinline__ void unpack2(ull v, float& lo, float& hi) {
    u32 a, b; asm("mov.b64 {%0, %1}, %2;" : "=r"(a), "=r"(b) : "l"(v));
    lo = __uint_as_float(a); hi = __uint_as_float(b);
}

// ---------------- 1) small zero ----------------
__global__ void zero_kernel() {
    int i = threadIdx.x;
    if (i < DD) { g_sum[i] = 0.f; g_sumsq[i] = 0.f; }
    for (int j = i; j < GG * (HH + XP); j += blockDim.x) g_gsum[j] = 0.f;
    if (i < GG) g_gcnt[i] = 0;
}

// ---------------- 2) batchnorm statistics ----------------
__global__ void bn_stats(const float* __restrict__ x, int n) {
    float s[DD], s2[DD];
#pragma unroll
    for (int d = 0; d < DD; d++) { s[d] = 0.f; s2[d] = 0.f; }
    for (int i = blockIdx.x * blockDim.x + threadIdx.x; i < n;
         i += gridDim.x * blockDim.x) {
#pragma unroll
        for (int d = 0; d < DD; d++) {
            float v = x[i * DD + d];
            s[d] += v; s2[d] += v * v;
        }
    }
#pragma unroll
    for (int d = 0; d < DD; d++) {
        for (int off = 16; off > 0; off >>= 1) {
            s[d]  += __shfl_down_sync(0xffffffffu, s[d], off);
            s2[d] += __shfl_down_sync(0xffffffffu, s2[d], off);
        }
    }
    if ((threadIdx.x & 31) == 0) {
#pragma unroll
        for (int d = 0; d < DD; d++) {
            atomicAdd(&g_sum[d], s[d]);
            atomicAdd(&g_sumsq[d], s2[d]);
        }
    }
}

// ---------------- 3) prep: stats + interleaved combined conv_w1 ----------------
__global__ void prep_kernel(const float* __restrict__ conv_w1, float invN) {
    int tid = threadIdx.x;
    if (tid < DD) {
        float mu  = g_sum[tid] * invN;
        float var = g_sumsq[tid] * invN - mu * mu;
        g_mean[tid] = mu;
        g_istd[tid] = rsqrtf(var + 1e-5f);
    }
    for (int i = tid; i < K1 * (WABROW / 2); i += blockDim.x) {
        int k = i / (WABROW / 2), a = i % (WABROW / 2);
        float wa = 0.f, wb = 0.f;
        if (a < FF) {
            float w0 = conv_w1[a * K1 + k];
            float w1 = conv_w1[(FF + a) * K1 + k];
            wa = w0 - w1; wb = w1;
        }
        g_wab[k * WABROW + 2 * a]     = wa;
        g_wab[k * WABROW + 2 * a + 1] = wb;
    }
}

// ---------------- 4) node kernel: BN + inputnet + packed u/v + zero acc ----------------
__global__ void node_kernel(const float* __restrict__ x,
                            const float* __restrict__ gamma,
                            const float* __restrict__ beta,
                            const float* __restrict__ w1,
                            const float* __restrict__ b1,
                            const float* __restrict__ w2,
                            const float* __restrict__ b2,
                            const float* __restrict__ conv_b1,
                            int n) {
    __shared__ float s_w1[DD * HH], s_w2[HH * HH], s_b1[HH], s_b2[HH];
    __shared__ float s_gam[DD], s_bet[DD], s_mu[DD], s_is[DD];
    __shared__ float s_wab[K1 * WABROW];
    __shared__ ull   s_cbp[K1];
    for (int i = threadIdx.x; i < DD * HH; i += blockDim.x) s_w1[i] = w1[i];
    for (int i = threadIdx.x; i < HH * HH; i += blockDim.x) s_w2[i] = w2[i];
    for (int i = threadIdx.x; i < K1 * WABROW; i += blockDim.x) s_wab[i] = g_wab[i];
    if (threadIdx.x < K1)
        s_cbp[threadIdx.x] = (ull)__float_as_uint(conv_b1[threadIdx.x]);
    if (threadIdx.x < HH) { s_b1[threadIdx.x] = b1[threadIdx.x]; s_b2[threadIdx.x] = b2[threadIdx.x]; }
    if (threadIdx.x < DD) {
        s_gam[threadIdx.x] = gamma[threadIdx.x];
        s_bet[threadIdx.x] = beta[threadIdx.x];
        s_mu[threadIdx.x]  = g_mean[threadIdx.x];
        s_is[threadIdx.x]  = g_istd[threadIdx.x];
    }
    __syncthreads();
    int nn = blockIdx.x * blockDim.x + threadIdx.x;
    if (nn >= n) return;

    float X[DD];
#pragma unroll
    for (int d = 0; d < DD; d++)
        X[d] = (x[nn * DD + d] - s_mu[d]) * s_is[d] * s_gam[d] + s_bet[d];

    float h[HH];
#pragma unroll
    for (int j = 0; j < HH; j++) {
        float t = s_b1[j];
#pragma unroll
        for (int d = 0; d < DD; d++) t = fmaf(X[d], s_w1[d * HH + j], t);
        h[j] = fmaxf(t, 0.f);
    }
    ull fp[FF];
#pragma unroll
    for (int j = 0; j < HH; j++) {
        float t = s_b2[j];
#pragma unroll
        for (int k = 0; k < HH; k++) t = fmaf(h[k], s_w2[k * HH + j], t);
        fp[j] = pack2(tanh_fast(t));
    }
#pragma unroll
    for (int d = 0; d < DD; d++) fp[HH + d] = pack2(X[d]);

    float* xp = g_X + (size_t)nn * XP;
#pragma unroll
    for (int d = 0; d < DD; d++) xp[d] = X[d];
    xp[13] = 0.f; xp[14] = 0.f; xp[15] = 0.f;

    // zero this node's accumulator row
    float4 z = make_float4(0.f, 0.f, 0.f, 0.f);
    float4* ar = (float4*)(g_acc + (size_t)nn * HH);
#pragma unroll
    for (int q = 0; q < 8; q++) ar[q] = z;

    float* up = g_u + (size_t)nn * K1;
    float* vp = g_v + (size_t)nn * K1;
#pragma unroll 1
    for (int k4 = 0; k4 < K1 / 4; k4++) {
        float uu[4], vv[4];
#pragma unroll
        for (int j = 0; j < 4; j++) {
            int k = 4 * k4 + j;
            ull a0 = s_cbp[k], a1 = 0ULL;
            const ulonglong2* wr = (const ulonglong2*)(s_wab + k * WABROW);
#pragma unroll
            for (int q = 0; q < 22; q++) {
                ulonglong2 w = wr[q];
                ffma2(a0, fp[2 * q], w.x);
                ffma2(a1, fp[2 * q + 1], w.y);
            }
            ull wl = ((const ull*)(s_wab + k * WABROW))[44];
            ffma2(a0, fp[44], wl);
            unpack2(add2(a0, a1), uu[j], vv[j]);
        }
        *(float4*)(up + 4 * k4) = make_float4(uu[0], uu[1], uu[2], uu[3]);
        *(float4*)(vp + 4 * k4) = make_float4(vv[0], vv[1], vv[2], vv[3]);
    }
}

// ---------------- 5) edge kernel: warp-local staging, no CTA barriers ----------------
__global__ void __launch_bounds__(128, 5)
edge_kernel(const int* __restrict__ ei,
            const float* __restrict__ conv_w2,
            const float* __restrict__ conv_b2,
            int E, int ntiles) {
    __shared__ float s_h1[TILE * H1STRIDE];   // 34816 B, warp w owns rows w*32..w*32+31
    __shared__ float s_w2[K1 * HH];           // 8192 B
    __shared__ ull   s_b2p[HH / 2];

    int tid = threadIdx.x;
    int wid = tid >> 5, lid = tid & 31;
    for (int i = tid; i < K1 * HH; i += 128) s_w2[i] = conv_w2[i];
    if (tid < HH / 2) s_b2p[tid] = ((const ull*)conv_b2)[tid];
    __syncthreads();

    int c4 = lid & 15;       // quad index within a row
    int hi16 = lid >> 4;     // which of the 2 rows this lane serves

    for (int tile = blockIdx.x; tile < ntiles; tile += gridDim.x) {
        int base = tile * TILE;
        int e = base + tid;
        bool val = e < E;
        int msrc = val ? ei[e] : 0;
        int mdst = val ? ei[E + e] : 0;

        // ---- stage h1 = relu(u[dst]+v[src]) for this warp's own 32 rows ----
#pragma unroll 8
        for (int s = 0; s < 16; s++) {
            int rl = 2 * s + hi16;                 // row within warp (0..31)
            int dn = __shfl_sync(0xffffffffu, mdst, rl);
            int sn = __shfl_sync(0xffffffffu, msrc, rl);
            float4 U = ((const float4*)(g_u + (size_t)dn * K1))[c4];
            float4 V = ((const float4*)(g_v + (size_t)sn * K1))[c4];
            float4 o;
            o.x = fmaxf(U.x + V.x, 0.f);
            o.y = fmaxf(U.y + V.y, 0.f);
            o.z = fmaxf(U.z + V.z, 0.f);
            o.w = fmaxf(U.w + V.w, 0.f);
            int row = (wid << 5) + rl;             // row within tile (0..127)
            *(float4*)(s_h1 + row * H1STRIDE + 4 * c4) = o;
        }
        __syncwarp();

        // ---- compute: 64x32 layer for this thread's edge ----
        ull h2[16];
#pragma unroll
        for (int q = 0; q < 16; q++) h2[q] = s_b2p[q];

        const float* hrow = s_h1 + tid * H1STRIDE;
#pragma unroll 2
        for (int q = 0; q < 16; q++) {
            float4 hq = *(const float4*)(hrow + 4 * q);
#pragma unroll
            for (int j = 0; j < 4; j++) {
                int k = 4 * q + j;
                float t = (j == 0) ? hq.x : (j == 1) ? hq.y : (j == 2) ? hq.z : hq.w;
                ull tp = pack2(t);
                const ulonglong2* wr = (const ulonglong2*)(s_w2 + (k << 5));
#pragma unroll
                for (int i = 0; i < 8; i++) {
                    ulonglong2 w = wr[i];
                    ffma2(h2[2 * i],     tp, w.x);
                    ffma2(h2[2 * i + 1], tp, w.y);
                }
            }
        }

        if (val) {
            float* ap = g_acc + (size_t)mdst * HH;
#pragma unroll
            for (int q = 0; q < 8; q++) {
                float a, b, c, d;
                unpack2(h2[2 * q], a, b);
                unpack2(h2[2 * q + 1], c, d);
                red_add_v4(ap + 4 * q, tanh_fast(a), tanh_fast(b),
                           tanh_fast(c), tanh_fast(d));
            }
        }
        __syncwarp();   // all lanes done reading this warp's rows before restage
    }
}

// ---------------- 6) global mean pool ----------------
__global__ void pool_kernel(const int* __restrict__ batch, int n) {
    int nn = blockIdx.x * blockDim.x + threadIdx.x;
    if (nn >= n) return;
    int g = batch[nn];
    const float4* ac = (const float4*)(g_acc + (size_t)nn * HH);
    const float4* xr = (const float4*)(g_X + (size_t)nn * XP);
    float* gs = g_gsum + (size_t)g * (HH + XP);
#pragma unroll
    for (int q = 0; q < 8; q++) {
        float4 v = ac[q];
        red_add_v4(gs + 4 * q, v.x, v.y, v.z, v.w);
    }
#pragma unroll
    for (int q = 0; q < 4; q++) {
        float4 v = xr[q];
        red_add_v4(gs + HH + 4 * q, v.x, v.y, v.z, v.w);
    }
    atomicAdd(&g_gcnt[g], 1);
}

// ---------------- 7) output MLP + sigmoid ----------------
__global__ void out_kernel(const float* __restrict__ w1,
                           const float* __restrict__ b1,
                           const float* __restrict__ w2,
                           const float* __restrict__ b2,
                           float* __restrict__ out, int gcount) {
    int g = blockIdx.x * blockDim.x + threadIdx.x;
    if (g >= gcount) return;
    float cnt = fmaxf((float)g_gcnt[g], 1.f);
    float inv = 1.f / cnt;
    float m[FF];
#pragma unroll
    for (int a = 0; a < FF; a++) m[a] = g_gsum[g * (HH + XP) + a] * inv;
    float o = b2[0];
    for (int h = 0; h < HH; h++) {
        float t = b1[h];
#pragma unroll
        for (int a = 0; a < FF; a++) t = fmaf(m[a], w1[a * HH + h], t);
        o = fmaf(fmaxf(t, 0.f), w2[h], o);
    }
    out[g] = 1.f / (1.f + expf(-o));
}

// ---------------- launch ----------------
extern "C" void kernel_launch(void* const* d_in, const int* in_sizes, int n_in,
                              void* d_out, int out_size) {
    const float* x     = (const float*)d_in[0];
    const int*   ei    = (const int*)d_in[1];
    const int*   batch = (const int*)d_in[2];
    const float* gamma = (const float*)d_in[3];
    const float* beta  = (const float*)d_in[4];
    const float* in_w1 = (const float*)d_in[5];
    const float* in_b1 = (const float*)d_in[6];
    const float* in_w2 = (const float*)d_in[7];
    const float* in_b2 = (const float*)d_in[8];
    const float* cw1   = (const float*)d_in[9];
    const float* cb1   = (const float*)d_in[10];
    const float* cw2   = (const float*)d_in[11];
    const float* cb2   = (const float*)d_in[12];
    const float* ow1   = (const float*)d_in[13];
    const float* ob1   = (const float*)d_in[14];
    const float* ow2   = (const float*)d_in[15];
    const float* ob2   = (const float*)d_in[16];

    int n = in_sizes[0] / DD;
    int E = in_sizes[1] / 2;
    int G = out_size;
    int ntiles = (E + TILE - 1) / TILE;
    int grid = 740;
    if (grid > ntiles) grid = ntiles;

    zero_kernel<<<1, 256>>>();
    bn_stats<<<148, 256>>>(x, n);
    prep_kernel<<<1, 256>>>(cw1, 1.f / (float)n);
    node_kernel<<<(n + 127) / 128, 128>>>(x, gamma, beta, in_w1, in_b1,
                                          in_w2, in_b2, cb1, n);
    edge_kernel<<<grid, 128>>>(ei, cw2, cb2, E, ntiles);
    pool_kernel<<<(n + 255) / 256, 256>>>(batch, n);
    out_kernel<<<1, 128>>>(ow1, ob1, ow2, ob2, (float*)d_out, G);
}